// round 12
// baseline (speedup 1.0000x reference)
#include <cuda_runtime.h>
#include <cuda_fp16.h>
#include <cstdint>

#define N_NODES 10000
#define N_EDGES 640000
#define HID 128
#define N_GRAPHS 64
#define EDGE_BLOCKS 625          // N_EDGES / 4 / 256 exactly
#define CONVW_BLOCKS 48          // 3*4096 float4 / 256

// ---------------- device scratch (no dynamic alloc allowed) ----------------
// g_deg is zero at module load; scan_kernel re-zeroes it after reading, so the
// histogram in pos_kernel always starts from zero (call-invariant).
__device__ int    g_deg[N_NODES];
__device__ float  g_dis[N_NODES];
__device__ float  g_pinv[N_GRAPHS];
__device__ int    g_rowptr[N_NODES + 1];
__device__ int    g_pos[N_EDGES];          // slot of edge within its dst row
__device__ int    g_col[N_EDGES];          // src ids grouped by dst (CSR)
__device__ __half g_bufA[N_NODES * HID];   // fp16 ping
__device__ __half g_bufB[N_NODES * HID];   // fp16 pong
__device__ __half g_w16[3 * HID * HID];    // fp16 weights

// ---------------- cp.async helpers ----------------
__device__ __forceinline__ void cp16(void* smem_dst, const void* gsrc) {
    uint32_t s = (uint32_t)__cvta_generic_to_shared(smem_dst);
    asm volatile("cp.async.cg.shared.global [%0], [%1], 16;" :: "r"(s), "l"(gsrc));
}
__device__ __forceinline__ void cp_commit() {
    asm volatile("cp.async.commit_group;" ::: "memory");
}
__device__ __forceinline__ void cp_wait0() {
    asm volatile("cp.async.wait_group 0;" ::: "memory");
}

__device__ __forceinline__ int lower_bound_dev(const int* __restrict__ a, int n, int key) {
    int lo = 0, hi = n;
    while (lo < hi) {
        int mid = (lo + hi) >> 1;
        if (a[mid] < key) lo = mid + 1; else hi = mid;
    }
    return lo;
}

// ---------------- pass 1: degree histogram w/ slot record + weight convert ----
__global__ __launch_bounds__(256) void pos_kernel(const int* __restrict__ dst,
                                                  const float* __restrict__ W0,
                                                  const float* __restrict__ W1,
                                                  const float* __restrict__ W2) {
    int b = blockIdx.x;
    if (b < EDGE_BLOCKS) {
        int base = (b * 256 + threadIdx.x) * 4;
        int4 d = *(const int4*)&dst[base];
        int p0 = atomicAdd(&g_deg[d.x], 1);
        int p1 = atomicAdd(&g_deg[d.y], 1);
        int p2 = atomicAdd(&g_deg[d.z], 1);
        int p3 = atomicAdd(&g_deg[d.w], 1);
        *(int4*)&g_pos[base] = make_int4(p0, p1, p2, p3);   // coalesced
    } else {
        int id = (b - EDGE_BLOCKS) * 256 + threadIdx.x;     // 0 .. 12287
        int m = id / 4096;
        int off = (id % 4096) * 4;
        const float* W = (m == 0) ? W0 : (m == 1) ? W1 : W2;
        float4 v = *(const float4*)&W[off];
        *(__half2*)&g_w16[m * HID * HID + off + 0] = __floats2half2_rn(v.x, v.y);
        *(__half2*)&g_w16[m * HID * HID + off + 2] = __floats2half2_rn(v.z, v.w);
    }
}

// ---------------- single-block scan: rowptr, dis, pinv, zero-out; re-zero deg --
__global__ void scan_kernel(const int* __restrict__ batch, float* __restrict__ out) {
    const int C = 10;  // 1024 * 10 >= N_NODES
    int tid = threadIdx.x;
    int lane = tid & 31;
    int wid = tid >> 5;
    int start = tid * C;
    int loc[C];
    int sum = 0;
#pragma unroll
    for (int i = 0; i < C; i++) {
        int idx = start + i;
        int d = (idx < N_NODES) ? g_deg[idx] : 0;
        loc[i] = d;
        sum += d;
    }
    int v = sum;
#pragma unroll
    for (int off = 1; off < 32; off <<= 1) {
        int u = __shfl_up_sync(0xffffffffu, v, off);
        if (lane >= off) v += u;
    }
    __shared__ int wsum[32];
    if (lane == 31) wsum[wid] = v;
    __syncthreads();
    if (wid == 0) {
        int w = wsum[lane];
#pragma unroll
        for (int off = 1; off < 32; off <<= 1) {
            int u = __shfl_up_sync(0xffffffffu, w, off);
            if (lane >= off) w += u;
        }
        wsum[lane] = w;
    }
    __syncthreads();
    int run = (wid > 0 ? wsum[wid - 1] : 0) + v - sum;   // exclusive prefix
#pragma unroll
    for (int i = 0; i < C; i++) {
        int idx = start + i;
        if (idx < N_NODES) {
            int d = loc[i];
            g_rowptr[idx] = run;
            g_dis[idx] = rsqrtf((float)(d + 1));
            g_deg[idx] = 0;              // restore invariant for next call
            run += d;
        }
    }
    if (tid == 1023) g_rowptr[N_NODES] = wsum[31];
    // zero the pooled-output accumulator (agg2 REDG-adds into it)
    for (int j = tid; j < N_GRAPHS * HID; j += 1024) out[j] = 0.0f;
    // per-graph inverse counts from sorted batch
    if (tid < N_GRAPHS) {
        int lo = lower_bound_dev(batch, N_NODES, tid);
        int hi = lower_bound_dev(batch, N_NODES, tid + 1);
        g_pinv[tid] = 1.0f / (float)max(hi - lo, 1);
    }
}

// ---------------- pass 2: CSR fill, pure scatter (no atomics) ----------------
__global__ __launch_bounds__(256) void fill_kernel(const int* __restrict__ src,
                                                   const int* __restrict__ dst) {
    int base = (blockIdx.x * 256 + threadIdx.x) * 4;
    int4 d = *(const int4*)&dst[base];
    int4 s = *(const int4*)&src[base];
    int4 p = *(const int4*)&g_pos[base];
    g_col[g_rowptr[d.x] + p.x] = s.x;
    g_col[g_rowptr[d.y] + p.y] = s.y;
    g_col[g_rowptr[d.z] + p.z] = s.z;
    g_col[g_rowptr[d.w] + p.w] = s.w;
}

// ---------------- fp16 tensor-core GEMM ----------------
// H = half((X @ W16) * dis[row]); fp16 W staged via cp.async.
#define TBM 32
#define SMH 136
#define GEMM_SMEM_BYTES ((TBM + 128) * SMH * 2)

template <typename TA>
__global__ __launch_bounds__(256) void gemm_kernel(const TA* __restrict__ X,
                                                   const __half* __restrict__ W16,
                                                   __half* __restrict__ H, int M) {
    extern __shared__ __half smh[];
    __half* Xs = smh;              // [TBM][SMH]
    __half* Ws = smh + TBM * SMH;  // [128][SMH]
    int tid = threadIdx.x;
    int lane = tid & 31;
    int wid = tid >> 5;
    int rb = blockIdx.x * TBM;

#pragma unroll
    for (int u = 0; u < 8; u++) {
        int id = tid + u * 256;
        int r = id >> 4;
        int c8 = (id & 15) * 8;
        cp16(&Ws[r * SMH + c8], &W16[r * HID + c8]);
    }
    cp_commit();

    if constexpr (sizeof(TA) == 4) {
#pragma unroll
        for (int u = 0; u < 4; u++) {
            int id = tid + u * 256;
            int r = id >> 5;
            int c4 = (id & 31) * 4;
            float4 v = make_float4(0.f, 0.f, 0.f, 0.f);
            if (rb + r < M) v = *(const float4*)&((const float*)X)[(rb + r) * HID + c4];
            *(__half2*)&Xs[r * SMH + c4 + 0] = __floats2half2_rn(v.x, v.y);
            *(__half2*)&Xs[r * SMH + c4 + 2] = __floats2half2_rn(v.z, v.w);
        }
    } else {
#pragma unroll
        for (int u = 0; u < 2; u++) {
            int id = tid + u * 256;
            int r = id >> 4;
            int c8 = (id & 15) * 8;
            uint4 v = make_uint4(0, 0, 0, 0);
            if (rb + r < M) v = *(const uint4*)&((const __half*)X)[(rb + r) * HID + c8];
            *(uint4*)&Xs[r * SMH + c8] = v;
        }
    }
    cp_wait0();
    __syncthreads();

    int gid = lane >> 2;
    int tig = lane & 3;
    int wm = wid & 1;        // M-slab (16 rows)
    int wn = wid >> 1;       // N-quarter (32 cols)
    int tr = lane & 7;
    int tt = lane >> 3;

    uint32_t xs_base = (uint32_t)__cvta_generic_to_shared(Xs);
    uint32_t ws_base = (uint32_t)__cvta_generic_to_shared(Ws);
    uint32_t a_addr0 = xs_base +
        (((wm * 16 + (tt & 1) * 8 + tr) * SMH + (tt >> 1) * 8) << 1);
    uint32_t b_addr0 = ws_base +
        ((((tt & 1) * 8 + tr) * SMH + wn * 32 + (tt >> 1) * 8) << 1);

    float d0[4], d1[4], d2[4], d3[4];
#pragma unroll
    for (int t = 0; t < 4; t++) { d0[t] = d1[t] = d2[t] = d3[t] = 0.f; }

#pragma unroll
    for (int k0 = 0; k0 < 128; k0 += 16) {
        uint32_t a0, a1, a2, a3;
        asm volatile("ldmatrix.sync.aligned.m8n8.x4.shared.b16 {%0,%1,%2,%3}, [%4];"
                     : "=r"(a0), "=r"(a1), "=r"(a2), "=r"(a3)
                     : "r"(a_addr0 + (k0 << 1)));
#pragma unroll
        for (int p = 0; p < 2; p++) {
            uint32_t b0a, b1a, b0b, b1b;
            asm volatile("ldmatrix.sync.aligned.m8n8.x4.trans.shared.b16 {%0,%1,%2,%3}, [%4];"
                         : "=r"(b0a), "=r"(b1a), "=r"(b0b), "=r"(b1b)
                         : "r"(b_addr0 + ((k0 * SMH + p * 16) << 1)));
            int t0 = 2 * p;
            int t1 = 2 * p + 1;
            asm volatile(
                "mma.sync.aligned.m16n8k16.row.col.f32.f16.f16.f32 "
                "{%0,%1,%2,%3}, {%4,%5,%6,%7}, {%8,%9}, {%0,%1,%2,%3};\n"
                : "+f"(d0[t0]), "+f"(d1[t0]), "+f"(d2[t0]), "+f"(d3[t0])
                : "r"(a0), "r"(a1), "r"(a2), "r"(a3), "r"(b0a), "r"(b1a));
            asm volatile(
                "mma.sync.aligned.m16n8k16.row.col.f32.f16.f16.f32 "
                "{%0,%1,%2,%3}, {%4,%5,%6,%7}, {%8,%9}, {%0,%1,%2,%3};\n"
                : "+f"(d0[t1]), "+f"(d1[t1]), "+f"(d2[t1]), "+f"(d3[t1])
                : "r"(a0), "r"(a1), "r"(a2), "r"(a3), "r"(b0b), "r"(b1b));
        }
    }

    int arow = wm * 16 + gid;
    int ncol = wn * 32;
    int r0 = rb + arow;
    int r1 = r0 + 8;
    float dis0 = (r0 < M) ? g_dis[r0] : 0.f;
    float dis1 = (r1 < M) ? g_dis[r1] : 0.f;
#pragma unroll
    for (int t = 0; t < 4; t++) {
        int c = ncol + t * 8 + tig * 2;
        if (r0 < M)
            *(__half2*)&H[r0 * HID + c] = __floats2half2_rn(d0[t] * dis0, d1[t] * dis0);
        if (r1 < M)
            *(__half2*)&H[r1 * HID + c] = __floats2half2_rn(d2[t] * dis1, d3[t] * dis1);
    }
}

// ---------------- aggregation: warp per node, 16-lane rows, 2 edges/iter -----
// Each lane loads uint4 (16B); half-warp covers a 256B row. fp16 chunk sums
// (chain 8) spill into fp32 master; halves combined via shfl_xor(16).
// POOL=1: scale by 1/count and REDG-add into out (mean pool fused).
template <int RELU, int POOL>
__global__ __launch_bounds__(256) void agg_kernel(const __half* __restrict__ HS_,
                                                  const float* __restrict__ bias,
                                                  __half* __restrict__ OUT16,
                                                  const int* __restrict__ batch,
                                                  float* __restrict__ out) {
    const uint4* HS4 = (const uint4*)HS_;   // 16 uint4 per 128-half row
    int node = (blockIdx.x * blockDim.x + threadIdx.x) >> 5;
    int lane = threadIdx.x & 31;
    if (node >= N_NODES) return;
    int hf = lane >> 4;
    int sub = lane & 15;
    int e0 = g_rowptr[node];
    int e1 = g_rowptr[node + 1];

    float m[8];
    if (hf == 0) {   // self-loop term into half 0
        uint4 sv = HS4[node * 16 + sub];
        const __half2* sh = (const __half2*)&sv;
#pragma unroll
        for (int k = 0; k < 4; k++) {
            float2 f = __half22float2(sh[k]);
            m[2 * k] = f.x; m[2 * k + 1] = f.y;
        }
    } else {
#pragma unroll
        for (int k = 0; k < 8; k++) m[k] = 0.f;
    }

    int n = e1 - e0;
    int nfull = n >> 5;
    int idx = e0 + lane;
    int s = (idx < e1) ? g_col[idx] : 0;

    for (int c = 0; c < nfull; c++) {
        int s_cur = s;
        int nidx = e0 + (c + 1) * 32 + lane;
        if (nidx < e1) s = g_col[nidx];
#pragma unroll
        for (int g8 = 0; g8 < 2; g8++) {
            uint4 v[8];
#pragma unroll
            for (int p = 0; p < 8; p++) {
                int ss = __shfl_sync(0xffffffffu, s_cur, (g8 * 8 + p) * 2 + hf);
                v[p] = HS4[ss * 16 + sub];
            }
            __half2 h[4];
            const __half2* v0 = (const __half2*)&v[0];
#pragma unroll
            for (int k = 0; k < 4; k++) h[k] = v0[k];
#pragma unroll
            for (int p = 1; p < 8; p++) {
                const __half2* vp = (const __half2*)&v[p];
#pragma unroll
                for (int k = 0; k < 4; k++) h[k] = __hadd2(h[k], vp[k]);
            }
#pragma unroll
            for (int k = 0; k < 4; k++) {
                float2 f = __half22float2(h[k]);
                m[2 * k] += f.x; m[2 * k + 1] += f.y;
            }
        }
    }
    int rem = n & 31;
    for (int p = 0; 2 * p < rem; p++) {
        int eidx = 2 * p + hf;
        int ss = __shfl_sync(0xffffffffu, s, eidx);
        if (eidx < rem) {
            uint4 v = HS4[ss * 16 + sub];
            const __half2* vp = (const __half2*)&v;
#pragma unroll
            for (int k = 0; k < 4; k++) {
                float2 f = __half22float2(vp[k]);
                m[2 * k] += f.x; m[2 * k + 1] += f.y;
            }
        }
    }
    // combine the two half-warp partials
#pragma unroll
    for (int k = 0; k < 8; k++)
        m[k] += __shfl_xor_sync(0xffffffffu, m[k], 16);

    float dsel = g_dis[node];
    float4 bb0 = *(const float4*)&bias[sub * 8 + 0];
    float4 bb1 = *(const float4*)&bias[sub * 8 + 4];
    float o[8];
    o[0] = m[0] * dsel + bb0.x; o[1] = m[1] * dsel + bb0.y;
    o[2] = m[2] * dsel + bb0.z; o[3] = m[3] * dsel + bb0.w;
    o[4] = m[4] * dsel + bb1.x; o[5] = m[5] * dsel + bb1.y;
    o[6] = m[6] * dsel + bb1.z; o[7] = m[7] * dsel + bb1.w;
    if (RELU) {
#pragma unroll
        for (int k = 0; k < 8; k++) o[k] = fmaxf(o[k], 0.f);
    }
    if (POOL) {
        if (hf == 0) {
            int g = batch[node];
            float inv = g_pinv[g];
#pragma unroll
            for (int k = 0; k < 8; k++)
                atomicAdd(&out[g * HID + sub * 8 + k], o[k] * inv);
        }
    } else {
        if (hf == 0) {
            uint4 pk;
            __half2* ph = (__half2*)&pk;
#pragma unroll
            for (int k = 0; k < 4; k++) ph[k] = __floats2half2_rn(o[2 * k], o[2 * k + 1]);
            ((uint4*)OUT16)[node * 16 + sub] = pk;
        }
    }
}

// ---------------- launch ----------------
extern "C" void kernel_launch(void* const* d_in, const int* in_sizes, int n_in,
                              void* d_out, int out_size) {
    const float* x     = (const float*)d_in[0];
    const int*   eidx  = (const int*)d_in[1];
    const int*   batch = (const int*)d_in[2];
    const float* W0    = (const float*)d_in[3];
    const float* b0    = (const float*)d_in[4];
    const float* W1    = (const float*)d_in[5];
    const float* b1    = (const float*)d_in[6];
    const float* W2    = (const float*)d_in[7];
    const float* b2    = (const float*)d_in[8];
    float* out = (float*)d_out;

    const int* src = eidx;
    const int* dst = eidx + N_EDGES;

    __half* bufA = nullptr;
    __half* bufB = nullptr;
    __half* w16 = nullptr;
    cudaGetSymbolAddress((void**)&bufA, g_bufA);
    cudaGetSymbolAddress((void**)&bufB, g_bufB);
    cudaGetSymbolAddress((void**)&w16, g_w16);

    static cudaStream_t s2 = nullptr;
    static cudaEvent_t evA = nullptr, evB = nullptr;
    if (!s2) {
        cudaFuncSetAttribute((const void*)gemm_kernel<float>,
                             cudaFuncAttributeMaxDynamicSharedMemorySize,
                             GEMM_SMEM_BYTES);
        cudaFuncSetAttribute((const void*)gemm_kernel<__half>,
                             cudaFuncAttributeMaxDynamicSharedMemorySize,
                             GEMM_SMEM_BYTES);
        cudaStreamCreateWithFlags(&s2, cudaStreamNonBlocking);
        cudaEventCreateWithFlags(&evA, cudaEventDisableTiming);
        cudaEventCreateWithFlags(&evB, cudaEventDisableTiming);
    }

    int gemm_grid = (N_NODES + TBM - 1) / TBM;   // 313
    int agg_grid = (N_NODES + 7) / 8;            // 1250

    // CSR pass 1 (+ fused weight convert) and prefix scan (+ pinv + zero out)
    pos_kernel<<<EDGE_BLOCKS + CONVW_BLOCKS, 256>>>(dst, W0, W1, W2);
    scan_kernel<<<1, 1024>>>(batch, out);

    // fork AFTER scan: gemm0 (needs w16 + dis) overlaps with fill
    cudaEventRecord(evA, 0);
    cudaStreamWaitEvent(s2, evA, 0);
    gemm_kernel<float><<<gemm_grid, 256, GEMM_SMEM_BYTES, s2>>>(x, w16, bufA, N_NODES);
    cudaEventRecord(evB, s2);

    fill_kernel<<<EDGE_BLOCKS, 256>>>(src, dst);

    cudaStreamWaitEvent(0, evB, 0);  // join before agg0

    // layer 0
    agg_kernel<1, 0><<<agg_grid, 256>>>(bufA, b0, bufB, batch, out);
    // layer 1
    gemm_kernel<__half><<<gemm_grid, 256, GEMM_SMEM_BYTES>>>(bufB, w16 + HID * HID, bufA, N_NODES);
    agg_kernel<1, 0><<<agg_grid, 256>>>(bufA, b1, bufB, batch, out);
    // layer 2
    gemm_kernel<__half><<<gemm_grid, 256, GEMM_SMEM_BYTES>>>(bufB, w16 + 2 * HID * HID, bufA, N_NODES);
    agg_kernel<0, 1><<<agg_grid, 256>>>(bufA, b2, nullptr, batch, out);
}

// round 13
// speedup vs baseline: 1.1894x; 1.1894x over previous
#include <cuda_runtime.h>
#include <cuda_fp16.h>
#include <cstdint>

#define N_NODES 10000
#define N_EDGES 640000
#define HID 128
#define N_GRAPHS 64
#define EDGE_BLOCKS 625          // N_EDGES / 4 / 256 exactly
#define CONVW_BLOCKS 48          // 3*4096 float4 / 256

// ---------------- device scratch (no dynamic alloc allowed) ----------------
// g_deg is zero at module load; scan_kernel re-zeroes it after reading, so the
// histogram in pos_kernel always starts from zero (call-invariant).
__device__ int    g_deg[N_NODES];
__device__ float  g_dis[N_NODES];
__device__ float  g_pinv[N_GRAPHS];
__device__ int    g_rowptr[N_NODES + 1];
__device__ int    g_pos[N_EDGES];          // slot of edge within its dst row
__device__ int    g_col[N_EDGES];          // src ids grouped by dst (CSR)
__device__ __half g_bufA[N_NODES * HID];   // fp16 ping
__device__ __half g_bufB[N_NODES * HID];   // fp16 pong
__device__ __half g_w16[3 * HID * HID];    // fp16 weights

// ---------------- cp.async helpers ----------------
__device__ __forceinline__ void cp16(void* smem_dst, const void* gsrc) {
    uint32_t s = (uint32_t)__cvta_generic_to_shared(smem_dst);
    asm volatile("cp.async.cg.shared.global [%0], [%1], 16;" :: "r"(s), "l"(gsrc));
}
__device__ __forceinline__ void cp_commit() {
    asm volatile("cp.async.commit_group;" ::: "memory");
}
__device__ __forceinline__ void cp_wait0() {
    asm volatile("cp.async.wait_group 0;" ::: "memory");
}

__device__ __forceinline__ int lower_bound_dev(const int* __restrict__ a, int n, int key) {
    int lo = 0, hi = n;
    while (lo < hi) {
        int mid = (lo + hi) >> 1;
        if (a[mid] < key) lo = mid + 1; else hi = mid;
    }
    return lo;
}

// ---------------- pass 1: degree histogram w/ slot record + weight convert ----
__global__ __launch_bounds__(256) void pos_kernel(const int* __restrict__ dst,
                                                  const float* __restrict__ W0,
                                                  const float* __restrict__ W1,
                                                  const float* __restrict__ W2) {
    int b = blockIdx.x;
    if (b < EDGE_BLOCKS) {
        int base = (b * 256 + threadIdx.x) * 4;
        int4 d = *(const int4*)&dst[base];
        int p0 = atomicAdd(&g_deg[d.x], 1);
        int p1 = atomicAdd(&g_deg[d.y], 1);
        int p2 = atomicAdd(&g_deg[d.z], 1);
        int p3 = atomicAdd(&g_deg[d.w], 1);
        *(int4*)&g_pos[base] = make_int4(p0, p1, p2, p3);   // coalesced
    } else {
        int id = (b - EDGE_BLOCKS) * 256 + threadIdx.x;     // 0 .. 12287
        int m = id / 4096;
        int off = (id % 4096) * 4;
        const float* W = (m == 0) ? W0 : (m == 1) ? W1 : W2;
        float4 v = *(const float4*)&W[off];
        *(__half2*)&g_w16[m * HID * HID + off + 0] = __floats2half2_rn(v.x, v.y);
        *(__half2*)&g_w16[m * HID * HID + off + 2] = __floats2half2_rn(v.z, v.w);
    }
}

// ---------------- single-block scan: rowptr, dis, pinv, zero-out; re-zero deg --
__global__ void scan_kernel(const int* __restrict__ batch, float* __restrict__ out) {
    const int C = 10;  // 1024 * 10 >= N_NODES
    int tid = threadIdx.x;
    int lane = tid & 31;
    int wid = tid >> 5;
    int start = tid * C;
    int loc[C];
    int sum = 0;
#pragma unroll
    for (int i = 0; i < C; i++) {
        int idx = start + i;
        int d = (idx < N_NODES) ? g_deg[idx] : 0;
        loc[i] = d;
        sum += d;
    }
    int v = sum;
#pragma unroll
    for (int off = 1; off < 32; off <<= 1) {
        int u = __shfl_up_sync(0xffffffffu, v, off);
        if (lane >= off) v += u;
    }
    __shared__ int wsum[32];
    if (lane == 31) wsum[wid] = v;
    __syncthreads();
    if (wid == 0) {
        int w = wsum[lane];
#pragma unroll
        for (int off = 1; off < 32; off <<= 1) {
            int u = __shfl_up_sync(0xffffffffu, w, off);
            if (lane >= off) w += u;
        }
        wsum[lane] = w;
    }
    __syncthreads();
    int run = (wid > 0 ? wsum[wid - 1] : 0) + v - sum;   // exclusive prefix
#pragma unroll
    for (int i = 0; i < C; i++) {
        int idx = start + i;
        if (idx < N_NODES) {
            int d = loc[i];
            g_rowptr[idx] = run;
            g_dis[idx] = rsqrtf((float)(d + 1));
            g_deg[idx] = 0;              // restore invariant for next call
            run += d;
        }
    }
    if (tid == 1023) g_rowptr[N_NODES] = wsum[31];
    // zero the pooled-output accumulator (final agg REDG-adds into it)
    for (int j = tid; j < N_GRAPHS * HID; j += 1024) out[j] = 0.0f;
    // per-graph inverse counts from sorted batch
    if (tid < N_GRAPHS) {
        int lo = lower_bound_dev(batch, N_NODES, tid);
        int hi = lower_bound_dev(batch, N_NODES, tid + 1);
        g_pinv[tid] = 1.0f / (float)max(hi - lo, 1);
    }
}

// ---------------- pass 2: CSR fill, pure scatter (no atomics) ----------------
__global__ __launch_bounds__(256) void fill_kernel(const int* __restrict__ src,
                                                   const int* __restrict__ dst) {
    int base = (blockIdx.x * 256 + threadIdx.x) * 4;
    int4 d = *(const int4*)&dst[base];
    int4 s = *(const int4*)&src[base];
    int4 p = *(const int4*)&g_pos[base];
    g_col[g_rowptr[d.x] + p.x] = s.x;
    g_col[g_rowptr[d.y] + p.y] = s.y;
    g_col[g_rowptr[d.z] + p.z] = s.z;
    g_col[g_rowptr[d.w] + p.w] = s.w;
}

// ---------------- fp16 tensor-core GEMM ----------------
// H = half((X @ W16) * dis[row]); fp16 W staged via cp.async.
#define TBM 32
#define SMH 136
#define GEMM_SMEM_BYTES ((TBM + 128) * SMH * 2)

template <typename TA>
__global__ __launch_bounds__(256) void gemm_kernel(const TA* __restrict__ X,
                                                   const __half* __restrict__ W16,
                                                   __half* __restrict__ H, int M) {
    extern __shared__ __half smh[];
    __half* Xs = smh;              // [TBM][SMH]
    __half* Ws = smh + TBM * SMH;  // [128][SMH]
    int tid = threadIdx.x;
    int lane = tid & 31;
    int wid = tid >> 5;
    int rb = blockIdx.x * TBM;

#pragma unroll
    for (int u = 0; u < 8; u++) {
        int id = tid + u * 256;
        int r = id >> 4;
        int c8 = (id & 15) * 8;
        cp16(&Ws[r * SMH + c8], &W16[r * HID + c8]);
    }
    cp_commit();

    if constexpr (sizeof(TA) == 4) {
#pragma unroll
        for (int u = 0; u < 4; u++) {
            int id = tid + u * 256;
            int r = id >> 5;
            int c4 = (id & 31) * 4;
            float4 v = make_float4(0.f, 0.f, 0.f, 0.f);
            if (rb + r < M) v = *(const float4*)&((const float*)X)[(rb + r) * HID + c4];
            *(__half2*)&Xs[r * SMH + c4 + 0] = __floats2half2_rn(v.x, v.y);
            *(__half2*)&Xs[r * SMH + c4 + 2] = __floats2half2_rn(v.z, v.w);
        }
    } else {
#pragma unroll
        for (int u = 0; u < 2; u++) {
            int id = tid + u * 256;
            int r = id >> 4;
            int c8 = (id & 15) * 8;
            uint4 v = make_uint4(0, 0, 0, 0);
            if (rb + r < M) v = *(const uint4*)&((const __half*)X)[(rb + r) * HID + c8];
            *(uint4*)&Xs[r * SMH + c8] = v;
        }
    }
    cp_wait0();
    __syncthreads();

    int gid = lane >> 2;
    int tig = lane & 3;
    int wm = wid & 1;        // M-slab (16 rows)
    int wn = wid >> 1;       // N-quarter (32 cols)
    int tr = lane & 7;
    int tt = lane >> 3;

    uint32_t xs_base = (uint32_t)__cvta_generic_to_shared(Xs);
    uint32_t ws_base = (uint32_t)__cvta_generic_to_shared(Ws);
    uint32_t a_addr0 = xs_base +
        (((wm * 16 + (tt & 1) * 8 + tr) * SMH + (tt >> 1) * 8) << 1);
    uint32_t b_addr0 = ws_base +
        ((((tt & 1) * 8 + tr) * SMH + wn * 32 + (tt >> 1) * 8) << 1);

    float d0[4], d1[4], d2[4], d3[4];
#pragma unroll
    for (int t = 0; t < 4; t++) { d0[t] = d1[t] = d2[t] = d3[t] = 0.f; }

#pragma unroll
    for (int k0 = 0; k0 < 128; k0 += 16) {
        uint32_t a0, a1, a2, a3;
        asm volatile("ldmatrix.sync.aligned.m8n8.x4.shared.b16 {%0,%1,%2,%3}, [%4];"
                     : "=r"(a0), "=r"(a1), "=r"(a2), "=r"(a3)
                     : "r"(a_addr0 + (k0 << 1)));
#pragma unroll
        for (int p = 0; p < 2; p++) {
            uint32_t b0a, b1a, b0b, b1b;
            asm volatile("ldmatrix.sync.aligned.m8n8.x4.trans.shared.b16 {%0,%1,%2,%3}, [%4];"
                         : "=r"(b0a), "=r"(b1a), "=r"(b0b), "=r"(b1b)
                         : "r"(b_addr0 + ((k0 * SMH + p * 16) << 1)));
            int t0 = 2 * p;
            int t1 = 2 * p + 1;
            asm volatile(
                "mma.sync.aligned.m16n8k16.row.col.f32.f16.f16.f32 "
                "{%0,%1,%2,%3}, {%4,%5,%6,%7}, {%8,%9}, {%0,%1,%2,%3};\n"
                : "+f"(d0[t0]), "+f"(d1[t0]), "+f"(d2[t0]), "+f"(d3[t0])
                : "r"(a0), "r"(a1), "r"(a2), "r"(a3), "r"(b0a), "r"(b1a));
            asm volatile(
                "mma.sync.aligned.m16n8k16.row.col.f32.f16.f16.f32 "
                "{%0,%1,%2,%3}, {%4,%5,%6,%7}, {%8,%9}, {%0,%1,%2,%3};\n"
                : "+f"(d0[t1]), "+f"(d1[t1]), "+f"(d2[t1]), "+f"(d3[t1])
                : "r"(a0), "r"(a1), "r"(a2), "r"(a3), "r"(b0b), "r"(b1b));
        }
    }

    int arow = wm * 16 + gid;
    int ncol = wn * 32;
    int r0 = rb + arow;
    int r1 = r0 + 8;
    float dis0 = (r0 < M) ? g_dis[r0] : 0.f;
    float dis1 = (r1 < M) ? g_dis[r1] : 0.f;
#pragma unroll
    for (int t = 0; t < 4; t++) {
        int c = ncol + t * 8 + tig * 2;
        if (r0 < M)
            *(__half2*)&H[r0 * HID + c] = __floats2half2_rn(d0[t] * dis0, d1[t] * dis0);
        if (r1 < M)
            *(__half2*)&H[r1 * HID + c] = __floats2half2_rn(d2[t] * dis1, d3[t] * dis1);
    }
}

// ---------------- gather body: fp16 chunk accumulation (chain 8) ------------
// (R11-validated) Each 8-edge sub-chunk sums in fp16 (2 HADD2/edge), spilled
// to the fp32 master accumulator.
__device__ __forceinline__ float4 gather_node(const uint2* __restrict__ HS,
                                              int node, int lane) {
    int e0 = g_rowptr[node];
    int e1 = g_rowptr[node + 1];
    float4 acc;
    {   // self-loop term (fp32)
        uint2 sv = HS[node * 32 + lane];
        float2 f0 = __half22float2(*(__half2*)&sv.x);
        float2 f1 = __half22float2(*(__half2*)&sv.y);
        acc.x = f0.x; acc.y = f0.y; acc.z = f1.x; acc.w = f1.y;
    }
    int n = e1 - e0;
    int nfull = n >> 5;
    int idx = e0 + lane;
    int s = (idx < e1) ? g_col[idx] : 0;
    for (int c = 0; c < nfull; c++) {
        int s_cur = s;
        int nidx = e0 + (c + 1) * 32 + lane;
        if (nidx < e1) s = g_col[nidx];
#pragma unroll
        for (int jj = 0; jj < 4; jj++) {
            uint2 v[8];
#pragma unroll
            for (int j2 = 0; j2 < 8; j2++) {
                int ss = __shfl_sync(0xffffffffu, s_cur, jj * 8 + j2);
                v[j2] = HS[ss * 32 + lane];
            }
            __half2 h0 = *(__half2*)&v[0].x;
            __half2 h1 = *(__half2*)&v[0].y;
#pragma unroll
            for (int j2 = 1; j2 < 8; j2++) {
                h0 = __hadd2(h0, *(__half2*)&v[j2].x);
                h1 = __hadd2(h1, *(__half2*)&v[j2].y);
            }
            float2 f0 = __half22float2(h0);
            float2 f1 = __half22float2(h1);
            acc.x += f0.x; acc.y += f0.y; acc.z += f1.x; acc.w += f1.y;
        }
    }
    int rem = n & 31;
    if (rem > 0) {   // tail in fp32 (cheap)
        for (int j = 0; j < rem; j++) {
            int ss = __shfl_sync(0xffffffffu, s, j);
            uint2 v = HS[ss * 32 + lane];
            float2 f0 = __half22float2(*(__half2*)&v.x);
            float2 f1 = __half22float2(*(__half2*)&v.y);
            acc.x += f0.x; acc.y += f0.y; acc.z += f1.x; acc.w += f1.y;
        }
    }
    return acc;
}

// ---------------- aggregation: warp per node, fp16 CSR gather ----------------
// POOL=0: write fp16 row (relu per RELU). POOL=1: mean-pool REDG into out.
template <int RELU, int POOL>
__global__ __launch_bounds__(256) void agg_kernel(const __half* __restrict__ HS_,
                                                  const float* __restrict__ bias,
                                                  __half* __restrict__ OUT16,
                                                  const int* __restrict__ batch,
                                                  float* __restrict__ out) {
    const uint2* HS = (const uint2*)HS_;
    int node = (blockIdx.x * blockDim.x + threadIdx.x) >> 5;
    int lane = threadIdx.x & 31;
    if (node >= N_NODES) return;
    float4 acc = gather_node(HS, node, lane);
    float dsel = g_dis[node];
    float4 bb = *(const float4*)&bias[lane * 4];
    float4 o;
    o.x = acc.x * dsel + bb.x;
    o.y = acc.y * dsel + bb.y;
    o.z = acc.z * dsel + bb.z;
    o.w = acc.w * dsel + bb.w;
    if (RELU) {
        o.x = fmaxf(o.x, 0.f); o.y = fmaxf(o.y, 0.f);
        o.z = fmaxf(o.z, 0.f); o.w = fmaxf(o.w, 0.f);
    }
    if (POOL) {
        int g = batch[node];
        float inv = g_pinv[g];
        atomicAdd(&out[g * HID + lane * 4 + 0], o.x * inv);
        atomicAdd(&out[g * HID + lane * 4 + 1], o.y * inv);
        atomicAdd(&out[g * HID + lane * 4 + 2], o.z * inv);
        atomicAdd(&out[g * HID + lane * 4 + 3], o.w * inv);
    } else {
        uint2 pk;
        *(__half2*)&pk.x = __floats2half2_rn(o.x, o.y);
        *(__half2*)&pk.y = __floats2half2_rn(o.z, o.w);
        ((uint2*)OUT16)[node * 32 + lane] = pk;
    }
}

// ---------------- launch ----------------
extern "C" void kernel_launch(void* const* d_in, const int* in_sizes, int n_in,
                              void* d_out, int out_size) {
    const float* x     = (const float*)d_in[0];
    const int*   eidx  = (const int*)d_in[1];
    const int*   batch = (const int*)d_in[2];
    const float* W0    = (const float*)d_in[3];
    const float* b0    = (const float*)d_in[4];
    const float* W1    = (const float*)d_in[5];
    const float* b1    = (const float*)d_in[6];
    const float* W2    = (const float*)d_in[7];
    const float* b2    = (const float*)d_in[8];
    float* out = (float*)d_out;

    const int* src = eidx;
    const int* dst = eidx + N_EDGES;

    __half* bufA = nullptr;
    __half* bufB = nullptr;
    __half* w16 = nullptr;
    cudaGetSymbolAddress((void**)&bufA, g_bufA);
    cudaGetSymbolAddress((void**)&bufB, g_bufB);
    cudaGetSymbolAddress((void**)&w16, g_w16);

    static cudaStream_t s2 = nullptr;
    static cudaEvent_t evA = nullptr, evB = nullptr;
    if (!s2) {
        cudaFuncSetAttribute((const void*)gemm_kernel<float>,
                             cudaFuncAttributeMaxDynamicSharedMemorySize,
                             GEMM_SMEM_BYTES);
        cudaFuncSetAttribute((const void*)gemm_kernel<__half>,
                             cudaFuncAttributeMaxDynamicSharedMemorySize,
                             GEMM_SMEM_BYTES);
        cudaStreamCreateWithFlags(&s2, cudaStreamNonBlocking);
        cudaEventCreateWithFlags(&evA, cudaEventDisableTiming);
        cudaEventCreateWithFlags(&evB, cudaEventDisableTiming);
    }

    int gemm_grid = (N_NODES + TBM - 1) / TBM;   // 313
    int agg_grid = (N_NODES + 7) / 8;            // 1250

    // CSR pass 1 (+ fused weight convert) and prefix scan (+ pinv + zero out)
    pos_kernel<<<EDGE_BLOCKS + CONVW_BLOCKS, 256>>>(dst, W0, W1, W2);
    scan_kernel<<<1, 1024>>>(batch, out);

    // fork AFTER scan: gemm0 (needs w16 + dis) overlaps with fill
    cudaEventRecord(evA, 0);
    cudaStreamWaitEvent(s2, evA, 0);
    gemm_kernel<float><<<gemm_grid, 256, GEMM_SMEM_BYTES, s2>>>(x, w16, bufA, N_NODES);
    cudaEventRecord(evB, s2);

    fill_kernel<<<EDGE_BLOCKS, 256>>>(src, dst);

    cudaStreamWaitEvent(0, evB, 0);  // join before agg0

    // layer 0
    agg_kernel<1, 0><<<agg_grid, 256>>>(bufA, b0, bufB, batch, out);
    // layer 1
    gemm_kernel<__half><<<gemm_grid, 256, GEMM_SMEM_BYTES>>>(bufB, w16 + HID * HID, bufA, N_NODES);
    agg_kernel<1, 0><<<agg_grid, 256>>>(bufA, b1, bufB, batch, out);
    // layer 2
    gemm_kernel<__half><<<gemm_grid, 256, GEMM_SMEM_BYTES>>>(bufB, w16 + 2 * HID * HID, bufA, N_NODES);
    agg_kernel<0, 1><<<agg_grid, 256>>>(bufA, b2, nullptr, batch, out);
}

// round 14
// speedup vs baseline: 1.3830x; 1.1628x over previous
#include <cuda_runtime.h>
#include <cuda_fp16.h>
#include <cstdint>

#define N_NODES 10000
#define N_EDGES 640000
#define HID 128
#define N_GRAPHS 64
#define EDGE_BLOCKS 625          // N_EDGES / 4 / 256 exactly
#define CONVW_BLOCKS 48          // 3*4096 float4 / 256

// ---------------- device scratch (no dynamic alloc allowed) ----------------
// g_deg is zero at module load; scan_kernel re-zeroes it after reading, so the
// histogram in pos_kernel always starts from zero (call-invariant).
__device__ int    g_deg[N_NODES];
__device__ float  g_dis[N_NODES];
__device__ int    g_rowptr[N_NODES + 1];
__device__ int    g_pos[N_EDGES];          // slot of edge within its dst row
__device__ int    g_col[N_EDGES];          // src ids grouped by dst (CSR)
__device__ __half g_bufA[N_NODES * HID];   // fp16 ping
__device__ __half g_bufB[N_NODES * HID];   // fp16 pong
__device__ __half g_w16[3 * HID * HID];    // fp16 weights

// ---------------- PDL helpers ----------------
__device__ __forceinline__ void pdl_wait() {
    asm volatile("griddepcontrol.wait;" ::: "memory");
}
__device__ __forceinline__ void pdl_trigger() {
    asm volatile("griddepcontrol.launch_dependents;" ::: "memory");
}

// ---------------- cp.async helpers ----------------
__device__ __forceinline__ void cp16(void* smem_dst, const void* gsrc) {
    uint32_t s = (uint32_t)__cvta_generic_to_shared(smem_dst);
    asm volatile("cp.async.cg.shared.global [%0], [%1], 16;" :: "r"(s), "l"(gsrc));
}
__device__ __forceinline__ void cp_commit() {
    asm volatile("cp.async.commit_group;" ::: "memory");
}
__device__ __forceinline__ void cp_wait0() {
    asm volatile("cp.async.wait_group 0;" ::: "memory");
}

// ---------------- pass 1: degree histogram w/ slot record + weight convert ----
__global__ __launch_bounds__(256) void pos_kernel(const int* __restrict__ dst,
                                                  const float* __restrict__ W0,
                                                  const float* __restrict__ W1,
                                                  const float* __restrict__ W2) {
    int b = blockIdx.x;
    if (b < EDGE_BLOCKS) {
        int base = (b * 256 + threadIdx.x) * 4;
        int4 d = *(const int4*)&dst[base];
        int p0 = atomicAdd(&g_deg[d.x], 1);
        int p1 = atomicAdd(&g_deg[d.y], 1);
        int p2 = atomicAdd(&g_deg[d.z], 1);
        int p3 = atomicAdd(&g_deg[d.w], 1);
        *(int4*)&g_pos[base] = make_int4(p0, p1, p2, p3);   // coalesced
    } else {
        int id = (b - EDGE_BLOCKS) * 256 + threadIdx.x;     // 0 .. 12287
        int m = id / 4096;
        int off = (id % 4096) * 4;
        const float* W = (m == 0) ? W0 : (m == 1) ? W1 : W2;
        float4 v = *(const float4*)&W[off];
        *(__half2*)&g_w16[m * HID * HID + off + 0] = __floats2half2_rn(v.x, v.y);
        *(__half2*)&g_w16[m * HID * HID + off + 2] = __floats2half2_rn(v.z, v.w);
    }
    pdl_trigger();
}

// ---------------- single-block scan (shuffle-based): rowptr, dis; re-zero deg --
__global__ void scan_kernel() {
    pdl_wait();                       // needs g_deg from pos
    const int C = 10;  // 1024 * 10 >= N_NODES
    int tid = threadIdx.x;
    int lane = tid & 31;
    int wid = tid >> 5;
    int start = tid * C;
    int loc[C];
    int sum = 0;
#pragma unroll
    for (int i = 0; i < C; i++) {
        int idx = start + i;
        int d = (idx < N_NODES) ? g_deg[idx] : 0;
        loc[i] = d;
        sum += d;
    }
    int v = sum;
#pragma unroll
    for (int off = 1; off < 32; off <<= 1) {
        int u = __shfl_up_sync(0xffffffffu, v, off);
        if (lane >= off) v += u;
    }
    __shared__ int wsum[32];
    if (lane == 31) wsum[wid] = v;
    __syncthreads();
    if (wid == 0) {
        int w = wsum[lane];
#pragma unroll
        for (int off = 1; off < 32; off <<= 1) {
            int u = __shfl_up_sync(0xffffffffu, w, off);
            if (lane >= off) w += u;
        }
        wsum[lane] = w;
    }
    __syncthreads();
    int run = (wid > 0 ? wsum[wid - 1] : 0) + v - sum;   // exclusive prefix
#pragma unroll
    for (int i = 0; i < C; i++) {
        int idx = start + i;
        if (idx < N_NODES) {
            int d = loc[i];
            g_rowptr[idx] = run;
            g_dis[idx] = rsqrtf((float)(d + 1));
            g_deg[idx] = 0;              // restore invariant for next call
            run += d;
        }
    }
    if (tid == 1023) g_rowptr[N_NODES] = wsum[31];
    pdl_trigger();
}

// ---------------- pass 2: CSR fill, pure scatter (no atomics) ----------------
__global__ __launch_bounds__(256) void fill_kernel(const int* __restrict__ src,
                                                   const int* __restrict__ dst) {
    int base = (blockIdx.x * 256 + threadIdx.x) * 4;
    // prologue: inputs + g_pos (from pos, 2 grids back -> flushed) are safe
    int4 d = *(const int4*)&dst[base];
    int4 s = *(const int4*)&src[base];
    int4 p = *(const int4*)&g_pos[base];
    pdl_wait();                       // rowptr from scan (immediate producer)
    g_col[g_rowptr[d.x] + p.x] = s.x;
    g_col[g_rowptr[d.y] + p.y] = s.y;
    g_col[g_rowptr[d.z] + p.z] = s.z;
    g_col[g_rowptr[d.w] + p.w] = s.w;
    pdl_trigger();
}

// ---------------- fp16 tensor-core GEMM ----------------
// H = half((X @ W16) * dis[row]); fp16 W staged via cp.async.
#define TBM 32
#define SMH 136
#define GEMM_SMEM_BYTES ((TBM + 128) * SMH * 2)

template <typename TA>
__global__ __launch_bounds__(256) void gemm_kernel(const TA* __restrict__ X,
                                                   const __half* __restrict__ W16,
                                                   __half* __restrict__ H, int M) {
    extern __shared__ __half smh[];
    __half* Xs = smh;              // [TBM][SMH]
    __half* Ws = smh + TBM * SMH;  // [128][SMH]
    int tid = threadIdx.x;
    int lane = tid & 31;
    int wid = tid >> 5;
    int rb = blockIdx.x * TBM;

    // prologue: w16 is >=2 grids back -> safe before wait
#pragma unroll
    for (int u = 0; u < 8; u++) {
        int id = tid + u * 256;
        int r = id >> 4;
        int c8 = (id & 15) * 8;
        cp16(&Ws[r * SMH + c8], &W16[r * HID + c8]);
    }
    cp_commit();

    pdl_wait();                       // X from the immediately preceding agg

    if constexpr (sizeof(TA) == 4) {
#pragma unroll
        for (int u = 0; u < 4; u++) {
            int id = tid + u * 256;
            int r = id >> 5;
            int c4 = (id & 31) * 4;
            float4 v = make_float4(0.f, 0.f, 0.f, 0.f);
            if (rb + r < M) v = *(const float4*)&((const float*)X)[(rb + r) * HID + c4];
            *(__half2*)&Xs[r * SMH + c4 + 0] = __floats2half2_rn(v.x, v.y);
            *(__half2*)&Xs[r * SMH + c4 + 2] = __floats2half2_rn(v.z, v.w);
        }
    } else {
#pragma unroll
        for (int u = 0; u < 2; u++) {
            int id = tid + u * 256;
            int r = id >> 4;
            int c8 = (id & 15) * 8;
            uint4 v = make_uint4(0, 0, 0, 0);
            if (rb + r < M) v = *(const uint4*)&((const __half*)X)[(rb + r) * HID + c8];
            *(uint4*)&Xs[r * SMH + c8] = v;
        }
    }
    cp_wait0();
    __syncthreads();

    int gid = lane >> 2;
    int tig = lane & 3;
    int wm = wid & 1;        // M-slab (16 rows)
    int wn = wid >> 1;       // N-quarter (32 cols)
    int tr = lane & 7;
    int tt = lane >> 3;

    uint32_t xs_base = (uint32_t)__cvta_generic_to_shared(Xs);
    uint32_t ws_base = (uint32_t)__cvta_generic_to_shared(Ws);
    uint32_t a_addr0 = xs_base +
        (((wm * 16 + (tt & 1) * 8 + tr) * SMH + (tt >> 1) * 8) << 1);
    uint32_t b_addr0 = ws_base +
        ((((tt & 1) * 8 + tr) * SMH + wn * 32 + (tt >> 1) * 8) << 1);

    float d0[4], d1[4], d2[4], d3[4];
#pragma unroll
    for (int t = 0; t < 4; t++) { d0[t] = d1[t] = d2[t] = d3[t] = 0.f; }

#pragma unroll
    for (int k0 = 0; k0 < 128; k0 += 16) {
        uint32_t a0, a1, a2, a3;
        asm volatile("ldmatrix.sync.aligned.m8n8.x4.shared.b16 {%0,%1,%2,%3}, [%4];"
                     : "=r"(a0), "=r"(a1), "=r"(a2), "=r"(a3)
                     : "r"(a_addr0 + (k0 << 1)));
#pragma unroll
        for (int p = 0; p < 2; p++) {
            uint32_t b0a, b1a, b0b, b1b;
            asm volatile("ldmatrix.sync.aligned.m8n8.x4.trans.shared.b16 {%0,%1,%2,%3}, [%4];"
                         : "=r"(b0a), "=r"(b1a), "=r"(b0b), "=r"(b1b)
                         : "r"(b_addr0 + ((k0 * SMH + p * 16) << 1)));
            int t0 = 2 * p;
            int t1 = 2 * p + 1;
            asm volatile(
                "mma.sync.aligned.m16n8k16.row.col.f32.f16.f16.f32 "
                "{%0,%1,%2,%3}, {%4,%5,%6,%7}, {%8,%9}, {%0,%1,%2,%3};\n"
                : "+f"(d0[t0]), "+f"(d1[t0]), "+f"(d2[t0]), "+f"(d3[t0])
                : "r"(a0), "r"(a1), "r"(a2), "r"(a3), "r"(b0a), "r"(b1a));
            asm volatile(
                "mma.sync.aligned.m16n8k16.row.col.f32.f16.f16.f32 "
                "{%0,%1,%2,%3}, {%4,%5,%6,%7}, {%8,%9}, {%0,%1,%2,%3};\n"
                : "+f"(d0[t1]), "+f"(d1[t1]), "+f"(d2[t1]), "+f"(d3[t1])
                : "r"(a0), "r"(a1), "r"(a2), "r"(a3), "r"(b0b), "r"(b1b));
        }
    }

    int arow = wm * 16 + gid;
    int ncol = wn * 32;
    int r0 = rb + arow;
    int r1 = r0 + 8;
    float dis0 = (r0 < M) ? g_dis[r0] : 0.f;
    float dis1 = (r1 < M) ? g_dis[r1] : 0.f;
#pragma unroll
    for (int t = 0; t < 4; t++) {
        int c = ncol + t * 8 + tig * 2;
        if (r0 < M)
            *(__half2*)&H[r0 * HID + c] = __floats2half2_rn(d0[t] * dis0, d1[t] * dis0);
        if (r1 < M)
            *(__half2*)&H[r1 * HID + c] = __floats2half2_rn(d2[t] * dis1, d3[t] * dis1);
    }
    pdl_trigger();
}

// ---------------- gather body: fp16 chunk accumulation (chain 8) ------------
// (R11-validated) pdl_wait sits after the index prologue, before first HS read.
__device__ __forceinline__ float4 gather_node(const uint2* __restrict__ HS,
                                              int node, int lane) {
    int e0 = g_rowptr[node];
    int e1 = g_rowptr[node + 1];
    int n = e1 - e0;
    int nfull = n >> 5;
    int idx = e0 + lane;
    int s = (idx < e1) ? g_col[idx] : 0;   // g_col >=2 grids back -> safe

    pdl_wait();                            // HS from the immediate producer

    float4 acc;
    {   // self-loop term (fp32)
        uint2 sv = HS[node * 32 + lane];
        float2 f0 = __half22float2(*(__half2*)&sv.x);
        float2 f1 = __half22float2(*(__half2*)&sv.y);
        acc.x = f0.x; acc.y = f0.y; acc.z = f1.x; acc.w = f1.y;
    }
    for (int c = 0; c < nfull; c++) {
        int s_cur = s;
        int nidx = e0 + (c + 1) * 32 + lane;
        if (nidx < e1) s = g_col[nidx];
#pragma unroll
        for (int jj = 0; jj < 4; jj++) {
            uint2 v[8];
#pragma unroll
            for (int j2 = 0; j2 < 8; j2++) {
                int ss = __shfl_sync(0xffffffffu, s_cur, jj * 8 + j2);
                v[j2] = HS[ss * 32 + lane];
            }
            __half2 h0 = *(__half2*)&v[0].x;
            __half2 h1 = *(__half2*)&v[0].y;
#pragma unroll
            for (int j2 = 1; j2 < 8; j2++) {
                h0 = __hadd2(h0, *(__half2*)&v[j2].x);
                h1 = __hadd2(h1, *(__half2*)&v[j2].y);
            }
            float2 f0 = __half22float2(h0);
            float2 f1 = __half22float2(h1);
            acc.x += f0.x; acc.y += f0.y; acc.z += f1.x; acc.w += f1.y;
        }
    }
    int rem = n & 31;
    if (rem > 0) {   // tail in fp32 (cheap)
        for (int j = 0; j < rem; j++) {
            int ss = __shfl_sync(0xffffffffu, s, j);
            uint2 v = HS[ss * 32 + lane];
            float2 f0 = __half22float2(*(__half2*)&v.x);
            float2 f1 = __half22float2(*(__half2*)&v.y);
            acc.x += f0.x; acc.y += f0.y; acc.z += f1.x; acc.w += f1.y;
        }
    }
    return acc;
}

// ---------------- aggregation: warp per node, fp16 CSR gather ----------------
__global__ __launch_bounds__(256) void agg_kernel(const __half* __restrict__ HS_,
                                                  const float* __restrict__ bias,
                                                  __half* __restrict__ OUT16, int relu) {
    const uint2* HS = (const uint2*)HS_;
    int node = (blockIdx.x * blockDim.x + threadIdx.x) >> 5;
    int lane = threadIdx.x & 31;
    if (node >= N_NODES) return;
    float4 acc = gather_node(HS, node, lane);
    float dsel = g_dis[node];
    float4 bb = *(const float4*)&bias[lane * 4];
    float4 o;
    o.x = acc.x * dsel + bb.x;
    o.y = acc.y * dsel + bb.y;
    o.z = acc.z * dsel + bb.z;
    o.w = acc.w * dsel + bb.w;
    if (relu) {
        o.x = fmaxf(o.x, 0.f); o.y = fmaxf(o.y, 0.f);
        o.z = fmaxf(o.z, 0.f); o.w = fmaxf(o.w, 0.f);
    }
    uint2 pk;
    *(__half2*)&pk.x = __floats2half2_rn(o.x, o.y);
    *(__half2*)&pk.y = __floats2half2_rn(o.z, o.w);
    ((uint2*)OUT16)[node * 32 + lane] = pk;
    pdl_trigger();
}

// ---------------- mean pool over sorted batch (fp16 input) ----------------
__device__ __forceinline__ int lower_bound_dev(const int* __restrict__ a, int n, int key) {
    int lo = 0, hi = n;
    while (lo < hi) {
        int mid = (lo + hi) >> 1;
        if (a[mid] < key) lo = mid + 1; else hi = mid;
    }
    return lo;
}

__global__ __launch_bounds__(256) void pool_kernel(const __half* __restrict__ H_,
                                                   const int* __restrict__ batch,
                                                   float* __restrict__ out) {
    const __half2* H2 = (const __half2*)H_;     // 64 half2 per row
    int g = blockIdx.x;
    int t = threadIdx.x;
    int lo = lower_bound_dev(batch, N_NODES, g);   // input-only prologue
    int hi = lower_bound_dev(batch, N_NODES, g + 1);
    pdl_wait();                                     // H from agg2
    int cp = t & 63;
    int rg = t >> 6;
    float sx = 0.f, sy = 0.f;
    int r = lo + rg;
    for (; r + 4 < hi; r += 8) {
        float2 f0 = __half22float2(H2[(r + 0) * 64 + cp]);
        float2 f1 = __half22float2(H2[(r + 4) * 64 + cp]);
        sx += f0.x + f1.x; sy += f0.y + f1.y;
    }
    for (; r < hi; r += 4) {
        float2 f = __half22float2(H2[r * 64 + cp]);
        sx += f.x; sy += f.y;
    }
    __shared__ float red[2][256];
    red[0][t] = sx;
    red[1][t] = sy;
    __syncthreads();
    if (t < 64) {
        float tx = red[0][t] + red[0][t + 64] + red[0][t + 128] + red[0][t + 192];
        float ty = red[1][t] + red[1][t + 64] + red[1][t + 128] + red[1][t + 192];
        float inv = 1.0f / (float)max(hi - lo, 1);
        out[g * HID + t * 2 + 0] = tx * inv;
        out[g * HID + t * 2 + 1] = ty * inv;
    }
}

// ---------------- launch ----------------
extern "C" void kernel_launch(void* const* d_in, const int* in_sizes, int n_in,
                              void* d_out, int out_size) {
    const float* x     = (const float*)d_in[0];
    const int*   eidx  = (const int*)d_in[1];
    const int*   batch = (const int*)d_in[2];
    const float* W0    = (const float*)d_in[3];
    const float* b0    = (const float*)d_in[4];
    const float* W1    = (const float*)d_in[5];
    const float* b1    = (const float*)d_in[6];
    const float* W2    = (const float*)d_in[7];
    const float* b2    = (const float*)d_in[8];
    float* out = (float*)d_out;

    const int* src = eidx;
    const int* dst = eidx + N_EDGES;

    __half* bufA = nullptr;
    __half* bufB = nullptr;
    __half* w16 = nullptr;
    cudaGetSymbolAddress((void**)&bufA, g_bufA);
    cudaGetSymbolAddress((void**)&bufB, g_bufB);
    cudaGetSymbolAddress((void**)&w16, g_w16);

    static cudaStream_t s2 = nullptr;
    static cudaEvent_t evA = nullptr, evB = nullptr;
    if (!s2) {
        cudaFuncSetAttribute((const void*)gemm_kernel<float>,
                             cudaFuncAttributeMaxDynamicSharedMemorySize,
                             GEMM_SMEM_BYTES);
        cudaFuncSetAttribute((const void*)gemm_kernel<__half>,
                             cudaFuncAttributeMaxDynamicSharedMemorySize,
                             GEMM_SMEM_BYTES);
        cudaStreamCreateWithFlags(&s2, cudaStreamNonBlocking);
        cudaEventCreateWithFlags(&evA, cudaEventDisableTiming);
        cudaEventCreateWithFlags(&evB, cudaEventDisableTiming);
    }

    int gemm_grid = (N_NODES + TBM - 1) / TBM;   // 313
    int agg_grid = (N_NODES + 7) / 8;            // 1250

    // PDL launch config (stream 0 serial chain)
    cudaLaunchAttribute pdl_attr[1];
    pdl_attr[0].id = cudaLaunchAttributeProgrammaticStreamSerialization;
    pdl_attr[0].val.programmaticStreamSerializationAllowed = 1;

    auto mkcfg = [&](int grid, int block, size_t smem) {
        cudaLaunchConfig_t c{};
        c.gridDim = dim3(grid, 1, 1);
        c.blockDim = dim3(block, 1, 1);
        c.dynamicSmemBytes = smem;
        c.stream = 0;
        c.attrs = pdl_attr;
        c.numAttrs = 1;
        return c;
    };

    // CSR pass 1 (+ fused weight convert): plain launch (head of chain)
    pos_kernel<<<EDGE_BLOCKS + CONVW_BLOCKS, 256>>>(dst, W0, W1, W2);

    // scan: PDL
    {
        cudaLaunchConfig_t c = mkcfg(1, 1024, 0);
        cudaLaunchKernelEx(&c, scan_kernel);
    }

    // fork AFTER scan: gemm0 (needs w16 + dis) overlaps with fill (plain)
    cudaEventRecord(evA, 0);
    cudaStreamWaitEvent(s2, evA, 0);
    gemm_kernel<float><<<gemm_grid, 256, GEMM_SMEM_BYTES, s2>>>(x, w16, bufA, N_NODES);
    cudaEventRecord(evB, s2);

    // fill: PDL (after scan on stream 0)
    {
        cudaLaunchConfig_t c = mkcfg(EDGE_BLOCKS, 256, 0);
        cudaLaunchKernelEx(&c, fill_kernel, src, dst);
    }

    cudaStreamWaitEvent(0, evB, 0);  // join before agg0

    // layer 0 (plain: dual dependency via event join)
    agg_kernel<<<agg_grid, 256>>>(bufA, b0, bufB, 1);
    // layer 1 (PDL chain from here)
    {
        cudaLaunchConfig_t c = mkcfg(gemm_grid, 256, GEMM_SMEM_BYTES);
        cudaLaunchKernelEx(&c, gemm_kernel<__half>,
                           (const __half*)bufB, (const __half*)(w16 + HID * HID),
                           (__half*)bufA, (int)N_NODES);
    }
    {
        cudaLaunchConfig_t c = mkcfg(agg_grid, 256, 0);
        cudaLaunchKernelEx(&c, agg_kernel,
                           (const __half*)bufA, b1, (__half*)bufB, 1);
    }
    // layer 2
    {
        cudaLaunchConfig_t c = mkcfg(gemm_grid, 256, GEMM_SMEM_BYTES);
        cudaLaunchKernelEx(&c, gemm_kernel<__half>,
                           (const __half*)bufB, (const __half*)(w16 + 2 * HID * HID),
                           (__half*)bufA, (int)N_NODES);
    }
    {
        cudaLaunchConfig_t c = mkcfg(agg_grid, 256, 0);
        cudaLaunchKernelEx(&c, agg_kernel,
                           (const __half*)bufA, b2, (__half*)bufB, 0);
    }
    // pool: PDL
    {
        cudaLaunchConfig_t c = mkcfg(N_GRAPHS, 256, 0);
        cudaLaunchKernelEx(&c, pool_kernel,
                           (const __half*)bufB, batch, out);
    }
}